// round 1
// baseline (speedup 1.0000x reference)
#include <cuda_runtime.h>

// HartleySpectralConv2d: B=16, CI=CO=64, H=W=256, modes 64x64.
// Strategy: partial DHT as dense GEMMs (only 64x64 central modes needed).
//
// Stages:
//  K0  build trig tables
//  Kw  transpose weight [io][xy] -> g_Wt[xy][io]
//  K1  forward stage 1:  U[img,m,j] = sum_n x[img,m,n] * T1[n,j]        (GEMM 262144x128x256)
//  K2  forward stage 2:  per-image R = T2(128x256) x U(256x128); combine -> C,S (mode-major)
//  K3  mode mixing:      total[b,o] = sum_i C*W + S*Wflip per mode
//  K4  inverse stage 1:  V[img,s1,(comp,n)] = Tot(64x64) x T4(64x512)
//  K5  inverse stage 2:  out = (A5(256x128) x V(128x256))/65536 + bias, ReLU

__device__ float g_T1[256 * 128];        // [n][j]   j<64: cos(2pi(j-32)n/256), j>=64: sin
__device__ float g_T2[128 * 256];        // [j][m]   transpose of T1
__device__ float g_T4[64 * 512];         // [s2][comp*256+n]  comp0 cos, comp1 sin
__device__ float g_A5[256 * 128];        // [m][2*s1+comp]    comp0 cas(+), comp1 cas(-)
__device__ float g_Wt[4096 * 4096];      // [s1*64+s2][i*64+o]      67 MB
__device__ float g_U[1024 * 256 * 128];  // [img][m][j]            134 MB
__device__ float g_CS[2 * 4096 * 1024];  // [comp][s1*64+s2][b*64+i] 33.5 MB
__device__ float g_Tt[1024 * 4096];      // [b*64+o][s1*64+s2]      16.8 MB
__device__ float g_V[1024 * 128 * 256];  // [img][s1*2+comp][n]    134 MB

// ---------------- K0: trig tables ----------------
__global__ void k_tables() {
    int a = blockIdx.x;      // 0..255 : spatial index (n or m)
    int b = threadIdx.x;     // 0..127
    int s = b & 63;          // mode slot
    int k = s - 32;          // signed frequency
    int q = ((k * a) % 256 + 256) % 256;
    float sv, cv;
    sincospif((float)q * (1.0f / 128.0f), &sv, &cv);   // angle = 2*pi*q/256
    float v = (b < 64) ? cv : sv;
    g_T1[a * 128 + b] = v;
    g_T2[b * 256 + a] = v;
    g_T4[s * 512 + (b >> 6) * 256 + a] = v;
    g_A5[a * 128 + 2 * s + (b >> 6)] = (b < 64) ? (cv + sv) : (cv - sv);
}

// ---------------- Kw: weight transpose ----------------
__global__ void k_wt(const float* __restrict__ w) {
    __shared__ float tile[32][33];
    int x0 = blockIdx.x * 32;   // xy
    int y0 = blockIdx.y * 32;   // io
    int tx = threadIdx.x, ty = threadIdx.y;   // (32, 8)
#pragma unroll
    for (int r = 0; r < 32; r += 8)
        tile[ty + r][tx] = w[(y0 + ty + r) * 4096 + x0 + tx];
    __syncthreads();
#pragma unroll
    for (int r = 0; r < 32; r += 8)
        g_Wt[(x0 + ty + r) * 4096 + y0 + tx] = tile[tx][ty + r];
}

// ---------------- K1: forward stage 1 ----------------
__global__ __launch_bounds__(256) void k_fwd1(const float* __restrict__ x) {
    __shared__ float As[128 * 32];
    __shared__ float Bs[32 * 128];
    const int row0 = blockIdx.x * 128;
    const int tid = threadIdx.x;
    const int ty = tid >> 4, tx = tid & 15;
    float acc[8][8];
#pragma unroll
    for (int i = 0; i < 8; i++)
#pragma unroll
        for (int j = 0; j < 8; j++) acc[i][j] = 0.f;

    for (int k0 = 0; k0 < 256; k0 += 32) {
#pragma unroll
        for (int t = 0; t < 4; t++) {
            int f = tid + t * 256;
            int r = f >> 3, c = (f & 7) << 2;
            *(float4*)&As[r * 32 + c] = *(const float4*)&x[(row0 + r) * 256 + k0 + c];
        }
#pragma unroll
        for (int t = 0; t < 4; t++) {
            int f = tid + t * 256;
            int kk = f >> 5, c = (f & 31) << 2;
            *(float4*)&Bs[kk * 128 + c] = *(const float4*)&g_T1[(k0 + kk) * 128 + c];
        }
        __syncthreads();
#pragma unroll
        for (int k = 0; k < 32; k++) {
            float a[8], b[8];
#pragma unroll
            for (int i = 0; i < 8; i++) a[i] = As[(ty * 8 + i) * 32 + k];
            float4 b0 = *(float4*)&Bs[k * 128 + tx * 8];
            float4 b1 = *(float4*)&Bs[k * 128 + tx * 8 + 4];
            b[0] = b0.x; b[1] = b0.y; b[2] = b0.z; b[3] = b0.w;
            b[4] = b1.x; b[5] = b1.y; b[6] = b1.z; b[7] = b1.w;
#pragma unroll
            for (int i = 0; i < 8; i++)
#pragma unroll
                for (int j = 0; j < 8; j++) acc[i][j] = fmaf(a[i], b[j], acc[i][j]);
        }
        __syncthreads();
    }
#pragma unroll
    for (int i = 0; i < 8; i++) {
        int r = row0 + ty * 8 + i;
        *(float4*)&g_U[r * 128 + tx * 8] =
            make_float4(acc[i][0], acc[i][1], acc[i][2], acc[i][3]);
        *(float4*)&g_U[r * 128 + tx * 8 + 4] =
            make_float4(acc[i][4], acc[i][5], acc[i][6], acc[i][7]);
    }
}

// ---------------- K2: forward stage 2 + even/odd combine ----------------
__global__ __launch_bounds__(256) void k_fwd2() {
    __shared__ float As[128 * 32];   // T2 slice [j][kk]
    __shared__ float Bs[32 * 128];   // U slice  [kk][j2]
    const int img = blockIdx.x;
    const float* Ub = &g_U[img * 256 * 128];
    const int tid = threadIdx.x;
    const int ty = tid >> 4, tx = tid & 15;
    const int s1b = ty * 4, s2b = tx * 4;
    float a00[4][4] = {}, a01[4][4] = {}, a10[4][4] = {}, a11[4][4] = {};

    for (int m0 = 0; m0 < 256; m0 += 32) {
#pragma unroll
        for (int t = 0; t < 4; t++) {
            int f = tid + t * 256;
            int j = f >> 3, c = (f & 7) << 2;
            *(float4*)&As[j * 32 + c] = *(const float4*)&g_T2[j * 256 + m0 + c];
        }
#pragma unroll
        for (int t = 0; t < 4; t++) {
            int f = tid + t * 256;
            int kk = f >> 5, c = (f & 31) << 2;
            *(float4*)&Bs[kk * 128 + c] = *(const float4*)&Ub[(m0 + kk) * 128 + c];
        }
        __syncthreads();
#pragma unroll
        for (int k = 0; k < 32; k++) {
            float al[4], ah[4], bl[4], bh[4];
#pragma unroll
            for (int i = 0; i < 4; i++) {
                al[i] = As[(s1b + i) * 32 + k];
                ah[i] = As[(64 + s1b + i) * 32 + k];
            }
            float4 bl4 = *(float4*)&Bs[k * 128 + s2b];
            float4 bh4 = *(float4*)&Bs[k * 128 + 64 + s2b];
            bl[0] = bl4.x; bl[1] = bl4.y; bl[2] = bl4.z; bl[3] = bl4.w;
            bh[0] = bh4.x; bh[1] = bh4.y; bh[2] = bh4.z; bh[3] = bh4.w;
#pragma unroll
            for (int i = 0; i < 4; i++)
#pragma unroll
                for (int j = 0; j < 4; j++) {
                    a00[i][j] = fmaf(al[i], bl[j], a00[i][j]);
                    a01[i][j] = fmaf(al[i], bh[j], a01[i][j]);
                    a10[i][j] = fmaf(ah[i], bl[j], a10[i][j]);
                    a11[i][j] = fmaf(ah[i], bh[j], a11[i][j]);
                }
        }
        __syncthreads();
    }
    // C = Cm*Uc - Sm*Us = a00 - a11 ; S = Sm*Uc + Cm*Us = a10 + a01
#pragma unroll
    for (int i = 0; i < 4; i++)
#pragma unroll
        for (int j = 0; j < 4; j++) {
            int s1 = s1b + i, s2 = s2b + j;
            g_CS[(s1 * 64 + s2) * 1024 + img] = a00[i][j] - a11[i][j];
            g_CS[4096 * 1024 + (s1 * 64 + s2) * 1024 + img] = a10[i][j] + a01[i][j];
        }
}

// ---------------- K3: per-mode channel mixing ----------------
__global__ __launch_bounds__(256) void k_mix() {
    __shared__ float sC[1024], sS[1024];
    __shared__ float sW[4096], sWr[4096];
    const int mode = blockIdx.x;
    const int s1 = mode >> 6, s2 = mode & 63;
    const int f1 = (64 - s1) & 63, f2 = (64 - s2) & 63;
    const int tid = threadIdx.x;
    for (int t = tid; t < 1024; t += 256) {
        sC[t] = g_CS[mode * 1024 + t];
        sS[t] = g_CS[4096 * 1024 + mode * 1024 + t];
    }
    for (int t = tid; t < 4096; t += 256) {
        sW[t] = g_Wt[mode * 4096 + t];
        sWr[t] = g_Wt[(f1 * 64 + f2) * 4096 + t];
    }
    __syncthreads();
    const int o = tid & 63, bq = tid >> 6;
    float acc[4] = {0.f, 0.f, 0.f, 0.f};
    for (int i = 0; i < 64; i++) {
        float w = sW[i * 64 + o];
        float wr = sWr[i * 64 + o];
#pragma unroll
        for (int r = 0; r < 4; r++) {
            int bc = (bq * 4 + r) * 64 + i;
            acc[r] = fmaf(sC[bc], w, fmaf(sS[bc], wr, acc[r]));
        }
    }
#pragma unroll
    for (int r = 0; r < 4; r++)
        g_Tt[((bq * 4 + r) * 64 + o) * 4096 + mode] = acc[r];
}

// ---------------- K4: inverse stage 1 ----------------
__global__ __launch_bounds__(256) void k_inv1() {
    __shared__ float As[64 * 64];    // Tot [s1][s2]
    __shared__ float Bs[64 * 128];   // T4 slice [s2][c]
    const int nh = blockIdx.x;       // 0..3 -> N cols [nh*128, nh*128+128)
    const int img = blockIdx.y;
    const int tid = threadIdx.x;
#pragma unroll
    for (int t = 0; t < 4; t++) {
        int f = tid + t * 256;
        *(float4*)&As[f * 4] = *(const float4*)&g_Tt[img * 4096 + f * 4];
    }
#pragma unroll
    for (int t = 0; t < 8; t++) {
        int f = tid + t * 256;
        int s2 = f >> 5, c = (f & 31) << 2;
        *(float4*)&Bs[s2 * 128 + c] = *(const float4*)&g_T4[s2 * 512 + nh * 128 + c];
    }
    __syncthreads();
    const int ty = tid >> 5, tx = tid & 31;   // rows ty*8..+7, cols tx*4..+3
    float acc[8][4] = {};
#pragma unroll
    for (int k = 0; k < 64; k++) {
        float a[8];
#pragma unroll
        for (int i = 0; i < 8; i++) a[i] = As[(ty * 8 + i) * 64 + k];
        float4 b4 = *(float4*)&Bs[k * 128 + tx * 4];
        float b[4] = {b4.x, b4.y, b4.z, b4.w};
#pragma unroll
        for (int i = 0; i < 8; i++)
#pragma unroll
            for (int j = 0; j < 4; j++) acc[i][j] = fmaf(a[i], b[j], acc[i][j]);
    }
    int col = nh * 128 + tx * 4;
    int comp = col >> 8, n = col & 255;
#pragma unroll
    for (int i = 0; i < 8; i++) {
        int s1 = ty * 8 + i;
        *(float4*)&g_V[((img * 64 + s1) * 2 + comp) * 256 + n] =
            make_float4(acc[i][0], acc[i][1], acc[i][2], acc[i][3]);
    }
}

// ---------------- K5: inverse stage 2 + bias + ReLU ----------------
__global__ __launch_bounds__(256) void k_inv2(const float* __restrict__ bias,
                                              float* __restrict__ out) {
    __shared__ float As[128 * 32];
    __shared__ float Bs[32 * 128];
    const int n0 = blockIdx.x * 128;
    const int m0 = blockIdx.y * 128;
    const int img = blockIdx.z;
    const float* Vb = &g_V[img * 128 * 256];
    const int tid = threadIdx.x;
    const int ty = tid >> 4, tx = tid & 15;
    float acc[8][8];
#pragma unroll
    for (int i = 0; i < 8; i++)
#pragma unroll
        for (int j = 0; j < 8; j++) acc[i][j] = 0.f;

    for (int k0 = 0; k0 < 128; k0 += 32) {
#pragma unroll
        for (int t = 0; t < 4; t++) {
            int f = tid + t * 256;
            int r = f >> 3, c = (f & 7) << 2;
            *(float4*)&As[r * 32 + c] = *(const float4*)&g_A5[(m0 + r) * 128 + k0 + c];
        }
#pragma unroll
        for (int t = 0; t < 4; t++) {
            int f = tid + t * 256;
            int kk = f >> 5, c = (f & 31) << 2;
            *(float4*)&Bs[kk * 128 + c] = *(const float4*)&Vb[(k0 + kk) * 256 + n0 + c];
        }
        __syncthreads();
#pragma unroll
        for (int k = 0; k < 32; k++) {
            float a[8], b[8];
#pragma unroll
            for (int i = 0; i < 8; i++) a[i] = As[(ty * 8 + i) * 32 + k];
            float4 b0 = *(float4*)&Bs[k * 128 + tx * 8];
            float4 b1 = *(float4*)&Bs[k * 128 + tx * 8 + 4];
            b[0] = b0.x; b[1] = b0.y; b[2] = b0.z; b[3] = b0.w;
            b[4] = b1.x; b[5] = b1.y; b[6] = b1.z; b[7] = b1.w;
#pragma unroll
            for (int i = 0; i < 8; i++)
#pragma unroll
                for (int j = 0; j < 8; j++) acc[i][j] = fmaf(a[i], b[j], acc[i][j]);
        }
        __syncthreads();
    }
    const float bv = bias[img & 63];
    const float sc = 1.0f / 65536.0f;
#pragma unroll
    for (int i = 0; i < 8; i++) {
        int m = m0 + ty * 8 + i;
        float v[8];
#pragma unroll
        for (int j = 0; j < 8; j++) v[j] = fmaxf(fmaf(acc[i][j], sc, bv), 0.f);
        *(float4*)&out[(img * 256 + m) * 256 + n0 + tx * 8] =
            make_float4(v[0], v[1], v[2], v[3]);
        *(float4*)&out[(img * 256 + m) * 256 + n0 + tx * 8 + 4] =
            make_float4(v[4], v[5], v[6], v[7]);
    }
}

extern "C" void kernel_launch(void* const* d_in, const int* in_sizes, int n_in,
                              void* d_out, int out_size) {
    const float* x = (const float*)d_in[0];     // [16,64,256,256]
    const float* w = (const float*)d_in[1];     // [64,64,64,64]
    const float* bias = (const float*)d_in[2];  // [64]
    float* out = (float*)d_out;                 // [16,64,256,256]

    k_tables<<<256, 128>>>();
    k_wt<<<dim3(128, 128), dim3(32, 8)>>>(w);
    k_fwd1<<<2048, 256>>>(x);
    k_fwd2<<<1024, 256>>>();
    k_mix<<<4096, 256>>>();
    k_inv1<<<dim3(4, 1024), 256>>>();
    k_inv2<<<dim3(2, 2, 1024), 256>>>(bias, out);
}

// round 2
// speedup vs baseline: 1.1989x; 1.1989x over previous
#include <cuda_runtime.h>

// HartleySpectralConv2d: B=16, CI=CO=64, H=W=256, modes 64x64.
// Partial DHT as dense GEMMs; inner loops use packed fp32 FFMA2 (fma.rn.f32x2).

using u64 = unsigned long long;

__device__ __forceinline__ u64 pack2(float lo, float hi) {
    u64 r; asm("mov.b64 %0, {%1, %2};" : "=l"(r) : "f"(lo), "f"(hi)); return r;
}
__device__ __forceinline__ float2 u2f(u64 v) {
    float2 f; asm("mov.b64 {%0, %1}, %2;" : "=f"(f.x), "=f"(f.y) : "l"(v)); return f;
}
__device__ __forceinline__ void fma2(u64& d, u64 a, u64 b) {
    asm("fma.rn.f32x2 %0, %1, %2, %0;" : "+l"(d) : "l"(a), "l"(b));
}

__device__ float g_T1[256 * 128];        // [n][j]   j<64: cos(2pi(j-32)n/256), j>=64: sin
__device__ float g_T2[128 * 256];        // [j][m]
__device__ float g_T4[64 * 512];         // [s2][comp*256+n]
__device__ float g_A5[256 * 128];        // [m][2*s1+comp]
__device__ float g_Wt[4096 * 4096];      // [s1*64+s2][i*64+o]
__device__ float g_U[1024 * 256 * 128];  // [img][m][j]
__device__ float g_CS[2 * 4096 * 1024];  // [comp][mode][ci*16 + b]
__device__ float g_Tt[1024 * 4096];      // [b*64+o][mode]
__device__ float g_V[1024 * 128 * 256];  // [img][s1*2+comp][n]

// ---------------- K0: trig tables ----------------
__global__ void k_tables() {
    int a = blockIdx.x;      // 0..255
    int b = threadIdx.x;     // 0..127
    int s = b & 63;
    int k = s - 32;
    int q = ((k * a) % 256 + 256) % 256;
    float sv, cv;
    sincospif((float)q * (1.0f / 128.0f), &sv, &cv);
    float v = (b < 64) ? cv : sv;
    g_T1[a * 128 + b] = v;
    g_T2[b * 256 + a] = v;
    g_T4[s * 512 + (b >> 6) * 256 + a] = v;
    g_A5[a * 128 + 2 * s + (b >> 6)] = (b < 64) ? (cv + sv) : (cv - sv);
}

// ---------------- Kw: weight transpose ----------------
__global__ void k_wt(const float* __restrict__ w) {
    __shared__ float tile[32][33];
    int x0 = blockIdx.x * 32;
    int y0 = blockIdx.y * 32;
    int tx = threadIdx.x, ty = threadIdx.y;
#pragma unroll
    for (int r = 0; r < 32; r += 8)
        tile[ty + r][tx] = w[(y0 + ty + r) * 4096 + x0 + tx];
    __syncthreads();
#pragma unroll
    for (int r = 0; r < 32; r += 8)
        g_Wt[(x0 + ty + r) * 4096 + y0 + tx] = tile[tx][ty + r];
}

// ---------------- K1: forward stage 1 ----------------
__global__ __launch_bounds__(256) void k_fwd1(const float* __restrict__ x) {
    __shared__ float As[128 * 32];
    __shared__ float Bs[32 * 128];
    const int row0 = blockIdx.x * 128;
    const int tid = threadIdx.x;
    const int ty = tid >> 4, tx = tid & 15;

    float4 pa[4], pb[4];
#pragma unroll
    for (int t = 0; t < 4; t++) {
        int f = tid + t * 256;
        int r = f >> 3, c = (f & 7) << 2;
        pa[t] = *(const float4*)&x[(row0 + r) * 256 + c];
        int kk = f >> 5, c2 = (f & 31) << 2;
        pb[t] = *(const float4*)&g_T1[kk * 128 + c2];
    }
    u64 acc[8][4];
#pragma unroll
    for (int i = 0; i < 8; i++)
#pragma unroll
        for (int j = 0; j < 4; j++) acc[i][j] = 0ull;

    for (int k0 = 0; k0 < 256; k0 += 32) {
        __syncthreads();
#pragma unroll
        for (int t = 0; t < 4; t++) {
            int f = tid + t * 256;
            int r = f >> 3, c = (f & 7) << 2;
            *(float4*)&As[r * 32 + c] = pa[t];
            int kk = f >> 5, c2 = (f & 31) << 2;
            *(float4*)&Bs[kk * 128 + c2] = pb[t];
        }
        __syncthreads();
        if (k0 + 32 < 256) {
#pragma unroll
            for (int t = 0; t < 4; t++) {
                int f = tid + t * 256;
                int r = f >> 3, c = (f & 7) << 2;
                pa[t] = *(const float4*)&x[(row0 + r) * 256 + k0 + 32 + c];
                int kk = f >> 5, c2 = (f & 31) << 2;
                pb[t] = *(const float4*)&g_T1[(k0 + 32 + kk) * 128 + c2];
            }
        }
#pragma unroll 8
        for (int k = 0; k < 32; k++) {
            u64 aa[8], bb[4];
#pragma unroll
            for (int i = 0; i < 8; i++) {
                float av = As[(ty * 8 + i) * 32 + k];
                aa[i] = pack2(av, av);
            }
#pragma unroll
            for (int j = 0; j < 4; j++)
                bb[j] = *(const u64*)&Bs[k * 128 + j * 32 + tx * 2];
#pragma unroll
            for (int i = 0; i < 8; i++)
#pragma unroll
                for (int j = 0; j < 4; j++) fma2(acc[i][j], aa[i], bb[j]);
        }
    }
#pragma unroll
    for (int i = 0; i < 8; i++) {
        int r = row0 + ty * 8 + i;
#pragma unroll
        for (int j = 0; j < 4; j++)
            *(float2*)&g_U[r * 128 + j * 32 + tx * 2] = u2f(acc[i][j]);
    }
}

// ---------------- K2: forward stage 2 + even/odd combine ----------------
__global__ __launch_bounds__(256) void k_fwd2() {
    __shared__ float As[128 * 32];   // T2 slice [j][kk]
    __shared__ float Bs[32 * 128];   // U slice  [kk][j2]
    const int img = blockIdx.x;
    const float* Ub = &g_U[img * 256 * 128];
    const int tid = threadIdx.x;
    const int ty = tid >> 4, tx = tid & 15;
    const int s1b = ty * 4;

    float4 pa[4], pb[4];
#pragma unroll
    for (int t = 0; t < 4; t++) {
        int f = tid + t * 256;
        int j = f >> 3, c = (f & 7) << 2;
        pa[t] = *(const float4*)&g_T2[j * 256 + c];
        int kk = f >> 5, c2 = (f & 31) << 2;
        pb[t] = *(const float4*)&Ub[kk * 128 + c2];
    }
    u64 a00[4][2], a01[4][2], a10[4][2], a11[4][2];
#pragma unroll
    for (int i = 0; i < 4; i++)
#pragma unroll
        for (int j = 0; j < 2; j++) {
            a00[i][j] = 0ull; a01[i][j] = 0ull; a10[i][j] = 0ull; a11[i][j] = 0ull;
        }

    for (int m0 = 0; m0 < 256; m0 += 32) {
        __syncthreads();
#pragma unroll
        for (int t = 0; t < 4; t++) {
            int f = tid + t * 256;
            int j = f >> 3, c = (f & 7) << 2;
            *(float4*)&As[j * 32 + c] = pa[t];
            int kk = f >> 5, c2 = (f & 31) << 2;
            *(float4*)&Bs[kk * 128 + c2] = pb[t];
        }
        __syncthreads();
        if (m0 + 32 < 256) {
#pragma unroll
            for (int t = 0; t < 4; t++) {
                int f = tid + t * 256;
                int j = f >> 3, c = (f & 7) << 2;
                pa[t] = *(const float4*)&g_T2[j * 256 + m0 + 32 + c];
                int kk = f >> 5, c2 = (f & 31) << 2;
                pb[t] = *(const float4*)&Ub[(m0 + 32 + kk) * 128 + c2];
            }
        }
#pragma unroll 8
        for (int k = 0; k < 32; k++) {
            u64 aal[4], aah[4], bbl[2], bbh[2];
#pragma unroll
            for (int i = 0; i < 4; i++) {
                float al = As[(s1b + i) * 32 + k];
                float ah = As[(64 + s1b + i) * 32 + k];
                aal[i] = pack2(al, al);
                aah[i] = pack2(ah, ah);
            }
#pragma unroll
            for (int j = 0; j < 2; j++) {
                bbl[j] = *(const u64*)&Bs[k * 128 + j * 32 + tx * 2];
                bbh[j] = *(const u64*)&Bs[k * 128 + 64 + j * 32 + tx * 2];
            }
#pragma unroll
            for (int i = 0; i < 4; i++)
#pragma unroll
                for (int j = 0; j < 2; j++) {
                    fma2(a00[i][j], aal[i], bbl[j]);
                    fma2(a01[i][j], aal[i], bbh[j]);
                    fma2(a10[i][j], aah[i], bbl[j]);
                    fma2(a11[i][j], aah[i], bbh[j]);
                }
        }
    }
    // C = a00 - a11 ; S = a10 + a01. Layout: g_CS[comp][mode][ci*16 + b]
    const int b = img >> 6, ic = img & 63;
#pragma unroll
    for (int i = 0; i < 4; i++)
#pragma unroll
        for (int j = 0; j < 2; j++) {
            int s1 = s1b + i, s2 = j * 32 + tx * 2;
            float2 c0 = u2f(a00[i][j]), c1 = u2f(a11[i][j]);
            float2 s0 = u2f(a10[i][j]), s1v = u2f(a01[i][j]);
            int m0i = (s1 * 64 + s2) * 1024 + ic * 16 + b;
            g_CS[m0i] = c0.x - c1.x;
            g_CS[m0i + 1024] = c0.y - c1.y;
            g_CS[4096 * 1024 + m0i] = s0.x + s1v.x;
            g_CS[4096 * 1024 + m0i + 1024] = s0.y + s1v.y;
        }
}

// ---------------- K3: per-mode channel mixing ----------------
__global__ __launch_bounds__(256) void k_mix() {
    __shared__ float sC[1024], sS[1024];
    __shared__ float sW[4096], sWr[4096];
    const int mode = blockIdx.x;
    const int s1 = mode >> 6, s2 = mode & 63;
    const int f1 = (64 - s1) & 63, f2 = (64 - s2) & 63;
    const int tid = threadIdx.x;
    for (int t = tid; t < 1024; t += 256) {
        sC[t] = g_CS[mode * 1024 + t];
        sS[t] = g_CS[4096 * 1024 + mode * 1024 + t];
    }
    for (int t = tid; t < 4096; t += 256) {
        sW[t] = g_Wt[mode * 4096 + t];
        sWr[t] = g_Wt[(f1 * 64 + f2) * 4096 + t];
    }
    __syncthreads();
    const int o = tid & 63, bq = tid >> 6;
    u64 acc01 = 0ull, acc23 = 0ull;
#pragma unroll 8
    for (int i = 0; i < 64; i++) {
        float w = sW[i * 64 + o];
        float wr = sWr[i * 64 + o];
        u64 ww = pack2(w, w), wwr = pack2(wr, wr);
        u64 c01 = *(const u64*)&sC[i * 16 + bq * 4];
        u64 c23 = *(const u64*)&sC[i * 16 + bq * 4 + 2];
        u64 s01 = *(const u64*)&sS[i * 16 + bq * 4];
        u64 s23 = *(const u64*)&sS[i * 16 + bq * 4 + 2];
        fma2(acc01, c01, ww);
        fma2(acc01, s01, wwr);
        fma2(acc23, c23, ww);
        fma2(acc23, s23, wwr);
    }
    float2 v01 = u2f(acc01), v23 = u2f(acc23);
    g_Tt[((bq * 4 + 0) * 64 + o) * 4096 + mode] = v01.x;
    g_Tt[((bq * 4 + 1) * 64 + o) * 4096 + mode] = v01.y;
    g_Tt[((bq * 4 + 2) * 64 + o) * 4096 + mode] = v23.x;
    g_Tt[((bq * 4 + 3) * 64 + o) * 4096 + mode] = v23.y;
}

// ---------------- K4: inverse stage 1 ----------------
__global__ __launch_bounds__(256) void k_inv1() {
    __shared__ float As[64 * 64];    // Tot [s1][s2]
    __shared__ float Bs[64 * 128];   // T4 slice [s2][c]
    const int nh = blockIdx.x;
    const int img = blockIdx.y;
    const int tid = threadIdx.x;
#pragma unroll
    for (int t = 0; t < 4; t++) {
        int f = tid + t * 256;
        *(float4*)&As[f * 4] = *(const float4*)&g_Tt[img * 4096 + f * 4];
    }
#pragma unroll
    for (int t = 0; t < 8; t++) {
        int f = tid + t * 256;
        int s2 = f >> 5, c = (f & 31) << 2;
        *(float4*)&Bs[s2 * 128 + c] = *(const float4*)&g_T4[s2 * 512 + nh * 128 + c];
    }
    __syncthreads();
    const int ty = tid >> 5, tx = tid & 31;
    u64 acc[8][2];
#pragma unroll
    for (int i = 0; i < 8; i++) { acc[i][0] = 0ull; acc[i][1] = 0ull; }
#pragma unroll 8
    for (int k = 0; k < 64; k++) {
        u64 aa[8], bb[2];
#pragma unroll
        for (int i = 0; i < 8; i++) {
            float av = As[(ty * 8 + i) * 64 + k];
            aa[i] = pack2(av, av);
        }
        bb[0] = *(const u64*)&Bs[k * 128 + tx * 2];
        bb[1] = *(const u64*)&Bs[k * 128 + 64 + tx * 2];
#pragma unroll
        for (int i = 0; i < 8; i++) {
            fma2(acc[i][0], aa[i], bb[0]);
            fma2(acc[i][1], aa[i], bb[1]);
        }
    }
#pragma unroll
    for (int i = 0; i < 8; i++) {
        int s1 = ty * 8 + i;
#pragma unroll
        for (int jj = 0; jj < 2; jj++) {
            int col = nh * 128 + jj * 64 + tx * 2;
            int comp = col >> 8, n = col & 255;
            *(float2*)&g_V[((img * 64 + s1) * 2 + comp) * 256 + n] = u2f(acc[i][jj]);
        }
    }
}

// ---------------- K5: inverse stage 2 + bias + ReLU ----------------
__global__ __launch_bounds__(256) void k_inv2(const float* __restrict__ bias,
                                              float* __restrict__ out) {
    __shared__ float As[128 * 32];
    __shared__ float Bs[32 * 128];
    const int n0 = blockIdx.x * 128;
    const int m0 = blockIdx.y * 128;
    const int img = blockIdx.z;
    const float* Vb = &g_V[img * 128 * 256];
    const int tid = threadIdx.x;
    const int ty = tid >> 4, tx = tid & 15;

    float4 pa[4], pb[4];
#pragma unroll
    for (int t = 0; t < 4; t++) {
        int f = tid + t * 256;
        int r = f >> 3, c = (f & 7) << 2;
        pa[t] = *(const float4*)&g_A5[(m0 + r) * 128 + c];
        int kk = f >> 5, c2 = (f & 31) << 2;
        pb[t] = *(const float4*)&Vb[kk * 256 + n0 + c2];
    }
    u64 acc[8][4];
#pragma unroll
    for (int i = 0; i < 8; i++)
#pragma unroll
        for (int j = 0; j < 4; j++) acc[i][j] = 0ull;

    for (int k0 = 0; k0 < 128; k0 += 32) {
        __syncthreads();
#pragma unroll
        for (int t = 0; t < 4; t++) {
            int f = tid + t * 256;
            int r = f >> 3, c = (f & 7) << 2;
            *(float4*)&As[r * 32 + c] = pa[t];
            int kk = f >> 5, c2 = (f & 31) << 2;
            *(float4*)&Bs[kk * 128 + c2] = pb[t];
        }
        __syncthreads();
        if (k0 + 32 < 128) {
#pragma unroll
            for (int t = 0; t < 4; t++) {
                int f = tid + t * 256;
                int r = f >> 3, c = (f & 7) << 2;
                pa[t] = *(const float4*)&g_A5[(m0 + r) * 128 + k0 + 32 + c];
                int kk = f >> 5, c2 = (f & 31) << 2;
                pb[t] = *(const float4*)&Vb[(k0 + 32 + kk) * 256 + n0 + c2];
            }
        }
#pragma unroll 8
        for (int k = 0; k < 32; k++) {
            u64 aa[8], bb[4];
#pragma unroll
            for (int i = 0; i < 8; i++) {
                float av = As[(ty * 8 + i) * 32 + k];
                aa[i] = pack2(av, av);
            }
#pragma unroll
            for (int j = 0; j < 4; j++)
                bb[j] = *(const u64*)&Bs[k * 128 + j * 32 + tx * 2];
#pragma unroll
            for (int i = 0; i < 8; i++)
#pragma unroll
                for (int j = 0; j < 4; j++) fma2(acc[i][j], aa[i], bb[j]);
        }
    }
    const float bv = bias[img & 63];
    const float sc = 1.0f / 65536.0f;
#pragma unroll
    for (int i = 0; i < 8; i++) {
        int m = m0 + ty * 8 + i;
#pragma unroll
        for (int j = 0; j < 4; j++) {
            float2 v = u2f(acc[i][j]);
            v.x = fmaxf(fmaf(v.x, sc, bv), 0.f);
            v.y = fmaxf(fmaf(v.y, sc, bv), 0.f);
            *(float2*)&out[(img * 256 + m) * 256 + n0 + j * 32 + tx * 2] = v;
        }
    }
}

extern "C" void kernel_launch(void* const* d_in, const int* in_sizes, int n_in,
                              void* d_out, int out_size) {
    const float* x = (const float*)d_in[0];     // [16,64,256,256]
    const float* w = (const float*)d_in[1];     // [64,64,64,64]
    const float* bias = (const float*)d_in[2];  // [64]
    float* out = (float*)d_out;                 // [16,64,256,256]

    k_tables<<<256, 128>>>();
    k_wt<<<dim3(128, 128), dim3(32, 8)>>>(w);
    k_fwd1<<<2048, 256>>>(x);
    k_fwd2<<<1024, 256>>>();
    k_mix<<<4096, 256>>>();
    k_inv1<<<dim3(4, 1024), 256>>>();
    k_inv2<<<dim3(2, 2, 1024), 256>>>(bias, out);
}